// round 1
// baseline (speedup 1.0000x reference)
#include <cuda_runtime.h>
#include <cstddef>

#define NQ 6
#define DIM 64
#define PI_F 3.14159265358979323846f
#define TILE 16
#define CHB 16

// ---------------- persistent scratch (no allocations allowed) ----------------
__device__ float2 g_U[DIM * DIM];      // fixed circuit unitary, row-major: phi_r = sum_k U[r][k] psi_k
__device__ float  g_styleAng[8 * NQ];  // tanh(style @ W^T + b) * pi, per batch

__device__ __forceinline__ float2 cmul(float2 a, float2 b) {
    return make_float2(a.x * b.x - a.y * b.y, a.x * b.y + a.y * b.x);
}
__device__ __forceinline__ float2 cadd(float2 a, float2 b) {
    return make_float2(a.x + b.x, a.y + b.y);
}

// ---------------- setup: build U (64x64) and style angles --------------------
// One block, 64 threads; thread j owns column j (circuit applied to basis |j>).
// Wire w maps to bit position (5 - w) of the flat state index.
__global__ void qcnn_setup_kernel(const float* __restrict__ style,
                                  const float* __restrict__ s2d_w,
                                  const float* __restrict__ s2d_b,
                                  const float* __restrict__ qrot,   // [2,6,2,3]
                                  const float* __restrict__ meas) { // [6,3]
    __shared__ float2 S[DIM][DIM];
    const int j = threadIdx.x;
    for (int k = 0; k < DIM; ++k) S[k][j] = make_float2(k == j ? 1.f : 0.f, 0.f);

    auto apply1q = [&](int w, float2 g00, float2 g01, float2 g10, float2 g11) {
        const int m = 1 << (5 - w);
        for (int k = 0; k < DIM; ++k) {
            if (k & m) continue;
            float2 a0 = S[k][j], a1 = S[k | m][j];
            S[k][j]     = cadd(cmul(g00, a0), cmul(g01, a1));
            S[k | m][j] = cadd(cmul(g10, a0), cmul(g11, a1));
        }
    };

    for (int l = 0; l < 2; ++l) {
        for (int i = 0; i < NQ; ++i) {
            float ry = qrot[((l * NQ + i) * 2 + 0) * 3 + 0];
            float c = cosf(0.5f * ry), s = sinf(0.5f * ry);
            apply1q(i, make_float2(c, 0.f), make_float2(-s, 0.f),
                       make_float2(s, 0.f), make_float2(c, 0.f));
            float rz = qrot[((l * NQ + i) * 2 + 1) * 3 + 0];
            float ch = cosf(0.5f * rz), sh = sinf(0.5f * rz);
            apply1q(i, make_float2(ch, -sh), make_float2(0.f, 0.f),
                       make_float2(0.f, 0.f), make_float2(ch, sh));
        }
        for (int i = 0; i < NQ; ++i) {           // ring CNOTs, sequential
            const int mc = 1 << (5 - i);
            const int mt = 1 << (5 - ((i + 1) % NQ));
            for (int k = 0; k < DIM; ++k) {
                if ((k & mc) && !(k & mt)) {
                    float2 t = S[k][j]; S[k][j] = S[k | mt][j]; S[k | mt][j] = t;
                }
            }
        }
    }
    for (int i = 0; i < NQ; ++i) {               // U3 measurement basis
        float th = meas[i * 3 + 0], ph = meas[i * 3 + 1], la = meas[i * 3 + 2];
        float ct = cosf(0.5f * th), st = sinf(0.5f * th);
        apply1q(i,
                make_float2(ct, 0.f),
                make_float2(-cosf(la) * st, -sinf(la) * st),
                make_float2(cosf(ph) * st,  sinf(ph) * st),
                make_float2(cosf(ph + la) * ct, sinf(ph + la) * ct));
    }
    __syncthreads();
    for (int r = 0; r < DIM; ++r) g_U[r * DIM + j] = S[r][j];

    if (j < 8 * NQ) {
        const int b = j / NQ, q = j % NQ;
        float acc = s2d_b[q];
        for (int d = 0; d < 128; ++d) acc += style[b * 128 + d] * s2d_w[q * 128 + d];
        g_styleAng[j] = tanhf(acc) * PI_F;
    }
}

// ---------------- main fused kernel ------------------------------------------
// One thread per output pixel. 16x16 pixel tile per 256-thread CTA.
// Channel-chunked staging: 16 input channels + their (64 res + 6 data) weights
// per chunk in shared; weight reads are uniform-broadcast LDS.128.
static constexpr int SXS    = 19;                 // padded row stride for halo tile
static constexpr int SM_U   = DIM * DIM * 8;      // 32768
static constexpr int SM_W   = 144 * 72 * 4;       // 41472
static constexpr int SM_X   = CHB * 18 * SXS * 4; // 21888
static constexpr int SM_TOT = SM_U + SM_W + SM_X + (384 + 64 + 64 + 8 + 8) * 4;

__global__ void __launch_bounds__(256) qcnn_main_kernel(
    const float* __restrict__ x,
    const float* __restrict__ data_w, const float* __restrict__ data_b,
    const float* __restrict__ res_w,  const float* __restrict__ res_b,
    const float* __restrict__ out_w,  const float* __restrict__ out_b,
    float* __restrict__ out)
{
    extern __shared__ unsigned char smraw[];
    float2* sU    = reinterpret_cast<float2*>(smraw);
    float*  sW    = reinterpret_cast<float*>(smraw + SM_U);
    float*  sX    = reinterpret_cast<float*>(smraw + SM_U + SM_W);
    float*  sOutW = sX + CHB * 18 * SXS;
    float*  sOutB = sOutW + 64 * NQ;
    float*  sResB = sOutB + 64;
    float*  sSty  = sResB + 64;
    float*  sDB   = sSty + 8;

    const int tid = threadIdx.x;
    const int bx = blockIdx.x * TILE, by = blockIdx.y * TILE, bb = blockIdx.z;
    const int tx = tid & 15, ty = tid >> 4;
    const int oh = by + ty, ow = bx + tx;

    for (int i = tid; i < DIM * DIM; i += 256) sU[i] = g_U[i];
    for (int i = tid; i < 64 * NQ; i += 256)   sOutW[i] = out_w[i];
    if (tid < 64) { sOutB[tid] = out_b[tid]; sResB[tid] = res_b[tid]; }
    if (tid < NQ) { sSty[tid] = g_styleAng[bb * NQ + tid]; sDB[tid] = data_b[tid]; }

    float acc[64];
#pragma unroll
    for (int i = 0; i < 64; ++i) acc[i] = 0.f;
    float aang[NQ] = {0, 0, 0, 0, 0, 0};

    for (int ch = 0; ch < 64; ch += CHB) {
        __syncthreads();   // previous chunk's compute done before overwrite
        // input halo tile: channels [ch, ch+16), rows/cols [-1, 17)
        for (int i = tid; i < CHB * 18 * 18; i += 256) {
            int cl = i / 324;
            int rem = i - cl * 324;
            int r = rem / 18, c = rem - r * 18;
            int gh = by + r - 1, gw = bx + c - 1;
            float v = 0.f;
            if ((unsigned)gh < 64u && (unsigned)gw < 64u)
                v = x[(((size_t)bb * 64 + ch + cl) * 64 + gh) * 64 + gw];
            sX[cl * (18 * SXS) + r * SXS + c] = v;
        }
        // transposed weight chunk: sW[p][co] with p = cl*9 + kpos
        for (int i = tid; i < 144 * 64; i += 256) {
            int p = i >> 6, co = i & 63;
            sW[p * 72 + co] = res_w[(size_t)co * 576 + ch * 9 + p];
        }
        for (int i = tid; i < 144 * NQ; i += 256) {
            int p = i / NQ, q = i - p * NQ;
            sW[p * 72 + 64 + q] = data_w[(size_t)q * 576 + ch * 9 + p];
        }
        __syncthreads();

        for (int cl = 0; cl < CHB; ++cl) {
            float v[9];
#pragma unroll
            for (int r = 0; r < 3; ++r)
#pragma unroll
                for (int c = 0; c < 3; ++c)
                    v[r * 3 + c] = sX[cl * (18 * SXS) + (ty + r) * SXS + (tx + c)];
#pragma unroll
            for (int kp = 0; kp < 9; ++kp) {
                const float val = v[kp];
                const float4* w4 = reinterpret_cast<const float4*>(&sW[(cl * 9 + kp) * 72]);
#pragma unroll
                for (int co4 = 0; co4 < 16; ++co4) {
                    float4 wv = w4[co4];
                    acc[co4 * 4 + 0] = fmaf(val, wv.x, acc[co4 * 4 + 0]);
                    acc[co4 * 4 + 1] = fmaf(val, wv.y, acc[co4 * 4 + 1]);
                    acc[co4 * 4 + 2] = fmaf(val, wv.z, acc[co4 * 4 + 2]);
                    acc[co4 * 4 + 3] = fmaf(val, wv.w, acc[co4 * 4 + 3]);
                }
                const float* wd = &sW[(cl * 9 + kp) * 72 + 64];
#pragma unroll
                for (int q = 0; q < NQ; ++q)
                    aang[q] = fmaf(val, wd[q], aang[q]);
            }
        }
    }

    // ---- quantum part: psi = lo (x) hi, phi = U psi, PauliZ expvals ----
    float cw[NQ], sw_[NQ];
#pragma unroll
    for (int q = 0; q < NQ; ++q) {
        float theta = tanhf(aang[q] + sDB[q]) * PI_F + sSty[q];
        cw[q]  = cosf(0.5f * theta);
        sw_[q] = sinf(0.5f * theta);
    }
    float A[8], Bv[8];
#pragma unroll
    for (int a = 0; a < 8; ++a) {
        A[a]  = (a & 4 ? sw_[0] : cw[0]) * (a & 2 ? sw_[1] : cw[1]) * (a & 1 ? sw_[2] : cw[2]);
        Bv[a] = (a & 4 ? sw_[3] : cw[3]) * (a & 2 ? sw_[4] : cw[4]) * (a & 1 ? sw_[5] : cw[5]);
    }
    float ev[NQ] = {0, 0, 0, 0, 0, 0};
#pragma unroll 4
    for (int r = 0; r < DIM; ++r) {
        float re = 0.f, im = 0.f;
        const float2* urow = &sU[r * DIM];
#pragma unroll
        for (int a = 0; a < 8; ++a) {
            float tre = 0.f, tim = 0.f;
#pragma unroll
            for (int b2 = 0; b2 < 8; ++b2) {
                float2 u = urow[a * 8 + b2];
                tre = fmaf(u.x, Bv[b2], tre);
                tim = fmaf(u.y, Bv[b2], tim);
            }
            re = fmaf(A[a], tre, re);
            im = fmaf(A[a], tim, im);
        }
        float p = fmaf(re, re, im * im);
#pragma unroll
        for (int q = 0; q < NQ; ++q) {
            float sgn = ((r >> (5 - q)) & 1) ? -1.f : 1.f;
            ev[q] = fmaf(sgn, p, ev[q]);
        }
    }

    // ---- epilogue: out[b, co, h, w] = res + biases + quant @ out_proj^T ----
    float* optr = out + (size_t)bb * 64 * 64 * 64 + (size_t)oh * 64 + ow;
#pragma unroll
    for (int co = 0; co < 64; ++co) {
        float o = acc[co] + sResB[co] + sOutB[co];
#pragma unroll
        for (int q = 0; q < NQ; ++q)
            o = fmaf(ev[q], sOutW[co * NQ + q], o);
        optr[(size_t)co * 4096] = o;
    }
}

// ---------------- launch ------------------------------------------------------
extern "C" void kernel_launch(void* const* d_in, const int* in_sizes, int n_in,
                              void* d_out, int out_size) {
    const float* x     = (const float*)d_in[0];
    const float* style = (const float*)d_in[1];
    const float* dpw   = (const float*)d_in[2];
    const float* dpb   = (const float*)d_in[3];
    const float* s2dw  = (const float*)d_in[4];
    const float* s2db  = (const float*)d_in[5];
    const float* qrot  = (const float*)d_in[6];
    const float* meas  = (const float*)d_in[7];
    const float* opw   = (const float*)d_in[8];
    const float* opb   = (const float*)d_in[9];
    const float* rpw   = (const float*)d_in[10];
    const float* rpb   = (const float*)d_in[11];
    float* out = (float*)d_out;

    cudaFuncSetAttribute(qcnn_main_kernel,
                         cudaFuncAttributeMaxDynamicSharedMemorySize, SM_TOT);

    qcnn_setup_kernel<<<1, 64>>>(style, s2dw, s2db, qrot, meas);
    qcnn_main_kernel<<<dim3(4, 4, 8), 256, SM_TOT>>>(x, dpw, dpb, rpw, rpb,
                                                     opw, opb, out);
}

// round 4
// speedup vs baseline: 1.8461x; 1.8461x over previous
#include <cuda_runtime.h>
#include <cstddef>

#define NQ 6
#define DIM 64
#define PI_F 3.14159265358979323846f

typedef unsigned long long ull;

// ---------------- persistent scratch ----------------
__device__ float2 g_U[DIM * DIM];      // fixed circuit unitary (row-major)
__device__ float  g_styleAng[8 * NQ];  // tanh(style @ W^T + b) * pi per batch

__device__ __forceinline__ float2 cmul(float2 a, float2 b) {
    return make_float2(a.x * b.x - a.y * b.y, a.x * b.y + a.y * b.x);
}
__device__ __forceinline__ float2 cadd(float2 a, float2 b) {
    return make_float2(a.x + b.x, a.y + b.y);
}

// packed f32x2 helpers (Blackwell FFMA2 path)
__device__ __forceinline__ ull pack2(float v) {
    ull r;
    asm("mov.b64 %0, {%1, %1};" : "=l"(r) : "r"(__float_as_uint(v)));
    return r;
}
__device__ __forceinline__ void fma2(ull& d, ull a, ull b) {
    asm("fma.rn.f32x2 %0, %1, %2, %0;" : "+l"(d) : "l"(a), "l"(b));
}
__device__ __forceinline__ float2 unpack2(ull v) {
    float2 f;
    asm("mov.b64 {%0, %1}, %2;" : "=f"(f.x), "=f"(f.y) : "l"(v));
    return f;
}

// ---------------- setup: build U (parallel) + style angles -------------------
__global__ void qcnn_setup_kernel(const float* __restrict__ style,
                                  const float* __restrict__ s2d_w,
                                  const float* __restrict__ s2d_b,
                                  const float* __restrict__ qrot,   // [2,6,2,3]
                                  const float* __restrict__ meas) { // [6,3]
    __shared__ float2 S[DIM][DIM];
    const int tid = threadIdx.x;   // 512 threads

    for (int i = tid; i < DIM * DIM; i += 512)
        S[i >> 6][i & 63] = make_float2((i >> 6) == (i & 63) ? 1.f : 0.f, 0.f);
    __syncthreads();

    auto apply = [&](int w, float2 g00, float2 g01, float2 g10, float2 g11) {
        const int m = 1 << (5 - w);
        for (int i = tid; i < 2048; i += 512) {
            int kidx = i >> 6, j = i & 63;
            int k = ((kidx & ~(m - 1)) << 1) | (kidx & (m - 1));
            float2 a0 = S[k][j], a1 = S[k | m][j];
            S[k][j]     = cadd(cmul(g00, a0), cmul(g01, a1));
            S[k | m][j] = cadd(cmul(g10, a0), cmul(g11, a1));
        }
        __syncthreads();
    };
    auto cnot = [&](int c, int t) {
        const int mc = 1 << (5 - c), mt = 1 << (5 - t);
        for (int i = tid; i < 4096; i += 512) {
            int k = i >> 6, j = i & 63;
            if ((k & mc) && !(k & mt)) {
                float2 tmp = S[k][j]; S[k][j] = S[k | mt][j]; S[k | mt][j] = tmp;
            }
        }
        __syncthreads();
    };

    for (int l = 0; l < 2; ++l) {
        for (int i = 0; i < NQ; ++i) {
            float ry = qrot[((l * NQ + i) * 2 + 0) * 3 + 0];
            float c = cosf(0.5f * ry), s = sinf(0.5f * ry);
            apply(i, make_float2(c, 0.f), make_float2(-s, 0.f),
                     make_float2(s, 0.f), make_float2(c, 0.f));
            float rz = qrot[((l * NQ + i) * 2 + 1) * 3 + 0];
            float ch = cosf(0.5f * rz), sh = sinf(0.5f * rz);
            apply(i, make_float2(ch, -sh), make_float2(0.f, 0.f),
                     make_float2(0.f, 0.f), make_float2(ch, sh));
        }
        for (int i = 0; i < NQ; ++i) cnot(i, (i + 1) % NQ);
    }
    for (int i = 0; i < NQ; ++i) {
        float th = meas[i * 3 + 0], ph = meas[i * 3 + 1], la = meas[i * 3 + 2];
        float ct = cosf(0.5f * th), st = sinf(0.5f * th);
        apply(i,
              make_float2(ct, 0.f),
              make_float2(-cosf(la) * st, -sinf(la) * st),
              make_float2(cosf(ph) * st,  sinf(ph) * st),
              make_float2(cosf(ph + la) * ct, sinf(ph + la) * ct));
    }

    for (int i = tid; i < DIM * DIM; i += 512)
        g_U[i] = S[i >> 6][i & 63];

    if (tid < 8 * NQ) {
        const int b = tid / NQ, q = tid % NQ;
        float acc = s2d_b[q];
        for (int d = 0; d < 128; ++d) acc += style[b * 128 + d] * s2d_w[q * 128 + d];
        g_styleAng[tid] = tanhf(acc) * PI_F;
    }
}

// ---------------- main fused kernel ------------------------------------------
// 256 threads/CTA, 16x16 pixel tile. Each thread: 2x2 pixel block x 16 channels.
// cg = warp-based channel group -> weight LDS are warp-uniform broadcasts.
// Data-proj padded to 8 slots, 2 slots per cg (cg3 gets zero pads).
static constexpr int SWS   = 76;                    // sW row stride (floats)
static constexpr int SM_U  = DIM * DIM * 8;         // 32768
static constexpr int SM_W  = 144 * SWS * 4;         // 43776
static constexpr int SM_X  = 16 * 342 * 4;          // 21888
static constexpr int SM_A  = 256 * 8 * 4;           // 8192
static constexpr int SM_TOT = SM_U + SM_W + SM_X + SM_A + (384 + 64 + 64 + 8 + 8) * 4;

__global__ void __launch_bounds__(256) qcnn_main_kernel(
    const float* __restrict__ x,
    const float* __restrict__ data_w, const float* __restrict__ data_b,
    const float* __restrict__ res_w,  const float* __restrict__ res_b,
    const float* __restrict__ out_w,  const float* __restrict__ out_b,
    float* __restrict__ out)
{
    extern __shared__ unsigned char smraw[];
    float2* sU   = reinterpret_cast<float2*>(smraw);
    float*  sW   = reinterpret_cast<float*>(smraw + SM_U);
    float*  sX   = reinterpret_cast<float*>(smraw + SM_U + SM_W);
    float*  sAng = reinterpret_cast<float*>(smraw + SM_U + SM_W + SM_X);
    float*  sOutW = sAng + 2048;
    float*  sOutB = sOutW + 384;
    float*  sResB = sOutB + 64;
    float*  sSty  = sResB + 64;
    float*  sDB   = sSty + 8;

    const int tid  = threadIdx.x;
    const int wid  = tid >> 5, lane = tid & 31;
    const int bx = blockIdx.x * 16, by = blockIdx.y * 16, bb = blockIdx.z;

    const int cg  = wid & 3;                 // channel group (warp-uniform)
    const int pb  = (wid >> 2) * 32 + lane;  // pixel block 0..63
    const int pbx = pb & 7, pby = pb >> 3;

    for (int i = tid; i < DIM * DIM; i += 256) sU[i] = g_U[i];
    for (int i = tid; i < 384; i += 256)       sOutW[i] = out_w[i];
    if (tid < 64) { sOutB[tid] = out_b[tid]; sResB[tid] = res_b[tid]; }
    if (tid < NQ) { sSty[tid] = g_styleAng[bb * NQ + tid]; sDB[tid] = data_b[tid]; }

    ull acc[4][8];     // 4 pixels x 8 channel-pairs
    ull accd[4];       // 4 pixels x 1 data-slot pair
#pragma unroll
    for (int p = 0; p < 4; ++p) {
        accd[p] = 0ull;
#pragma unroll
        for (int c = 0; c < 8; ++c) acc[p][c] = 0ull;
    }

    for (int ch = 0; ch < 64; ch += 16) {
        __syncthreads();
        // stage input halo tile [16ch x 18 x 18] (padded stride 19)
        for (int i = tid; i < 16 * 324; i += 256) {
            int cl = i / 324, rem = i - cl * 324;
            int r = rem / 18, c = rem - r * 18;
            int gh = by + r - 1, gw = bx + c - 1;
            float v = 0.f;
            if ((unsigned)gh < 64u && (unsigned)gw < 64u)
                v = x[(((size_t)bb * 64 + ch + cl) * 64 + gh) * 64 + gw];
            sX[cl * 342 + r * 19 + c] = v;
        }
        // stage res weights transposed: sW[p][co], coalesced LDG over p
        for (int i = tid; i < 64 * 144; i += 256) {
            int co = i / 144, p = i - co * 144;
            sW[p * SWS + co] = res_w[(size_t)co * 576 + ch * 9 + p];
        }
        // data weights (8 slots, 2 zero pads)
        for (int i = tid; i < 8 * 144; i += 256) {
            int q = i / 144, p = i - q * 144;
            sW[p * SWS + 64 + q] = (q < 6) ? data_w[(size_t)q * 576 + ch * 9 + p] : 0.f;
        }
        __syncthreads();

        const float* xb = sX + (2 * pby) * 19 + 2 * pbx;
        for (int cl = 0; cl < 16; ++cl) {
            ull w2[16];
#pragma unroll
            for (int y = 0; y < 4; ++y)
#pragma unroll
                for (int xx = 0; xx < 4; ++xx)
                    w2[y * 4 + xx] = pack2(xb[cl * 342 + y * 19 + xx]);

            const float* wb = sW + cl * 9 * SWS;
#pragma unroll
            for (int kp = 0; kp < 9; ++kp) {
                const int ky = kp / 3, kx = kp - ky * 3;
                const ulonglong2* wp = reinterpret_cast<const ulonglong2*>(wb + kp * SWS + cg * 16);
                ulonglong2 wA = wp[0], wB = wp[1], wC = wp[2], wD = wp[3];
                ull wd_ = *reinterpret_cast<const ull*>(wb + kp * SWS + 64 + cg * 2);
#pragma unroll
                for (int py = 0; py < 2; ++py)
#pragma unroll
                    for (int pxx = 0; pxx < 2; ++pxx) {
                        ull v = w2[(py + ky) * 4 + (pxx + kx)];
                        const int pi = py * 2 + pxx;
                        fma2(acc[pi][0], v, wA.x); fma2(acc[pi][1], v, wA.y);
                        fma2(acc[pi][2], v, wB.x); fma2(acc[pi][3], v, wB.y);
                        fma2(acc[pi][4], v, wC.x); fma2(acc[pi][5], v, wC.y);
                        fma2(acc[pi][6], v, wD.x); fma2(acc[pi][7], v, wD.y);
                        fma2(accd[pi], v, wd_);
                    }
            }
        }
    }

    // publish data-angle partials (slots cg*2, cg*2+1); cg3 holds pads
#pragma unroll
    for (int pi = 0; pi < 4; ++pi) {
        float2 ad = unpack2(accd[pi]);
        int py = pi >> 1, pxx = pi & 1;
        int pix = (2 * pby + py) * 16 + 2 * pbx + pxx;
        if (cg < 3) {
            sAng[pix * 8 + cg * 2 + 0] = ad.x;
            sAng[pix * 8 + cg * 2 + 1] = ad.y;
        }
    }
    __syncthreads();

    // ---- quantum: thread t owns pixel t ----
    {
        float cw[NQ], sw_[NQ];
#pragma unroll
        for (int q = 0; q < NQ; ++q) {
            float th = tanhf(sAng[tid * 8 + q] + sDB[q]) * PI_F + sSty[q];
            cw[q]  = cosf(0.5f * th);
            sw_[q] = sinf(0.5f * th);
        }
        float A[8], Bv[8];
#pragma unroll
        for (int a = 0; a < 8; ++a) {
            A[a]  = (a & 4 ? sw_[0] : cw[0]) * (a & 2 ? sw_[1] : cw[1]) * (a & 1 ? sw_[2] : cw[2]);
            Bv[a] = (a & 4 ? sw_[3] : cw[3]) * (a & 2 ? sw_[4] : cw[4]) * (a & 1 ? sw_[5] : cw[5]);
        }
        ull adup[8], bdup[8];
#pragma unroll
        for (int a = 0; a < 8; ++a) { adup[a] = pack2(A[a]); bdup[a] = pack2(Bv[a]); }

        float ev[NQ] = {0, 0, 0, 0, 0, 0};
#pragma unroll 4
        for (int r = 0; r < DIM; ++r) {
            const ulonglong2* u4 = reinterpret_cast<const ulonglong2*>(sU + r * DIM);
            ull racc = 0ull;
#pragma unroll
            for (int a = 0; a < 8; ++a) {
                ull t = 0ull;
#pragma unroll
                for (int bq = 0; bq < 4; ++bq) {
                    ulonglong2 uu = u4[a * 4 + bq];
                    fma2(t, uu.x, bdup[2 * bq]);
                    fma2(t, uu.y, bdup[2 * bq + 1]);
                }
                fma2(racc, adup[a], t);
            }
            float2 ri = unpack2(racc);
            float pr = fmaf(ri.x, ri.x, ri.y * ri.y);
#pragma unroll
            for (int q = 0; q < NQ; ++q)
                ev[q] += ((r >> (5 - q)) & 1) ? -pr : pr;
        }
#pragma unroll
        for (int q = 0; q < NQ; ++q) sAng[tid * 8 + q] = ev[q];
    }
    __syncthreads();

    // ---- epilogue ----
#pragma unroll
    for (int pi = 0; pi < 4; ++pi) {
        int py = pi >> 1, pxx = pi & 1;
        int prow = 2 * pby + py, pcol = 2 * pbx + pxx;
        int pix = prow * 16 + pcol;
        float e[NQ];
#pragma unroll
        for (int q = 0; q < NQ; ++q) e[q] = sAng[pix * 8 + q];
        float* op = out + (size_t)bb * 262144 + (size_t)(cg * 16) * 4096
                        + (by + prow) * 64 + (bx + pcol);
#pragma unroll
        for (int c2 = 0; c2 < 8; ++c2) {
            float2 av = unpack2(acc[pi][c2]);
            int ch0 = cg * 16 + 2 * c2;
            float o0 = av.x + sResB[ch0]     + sOutB[ch0];
            float o1 = av.y + sResB[ch0 + 1] + sOutB[ch0 + 1];
            const float* w0 = sOutW + ch0 * 6;
            const float* w1 = w0 + 6;
#pragma unroll
            for (int q = 0; q < NQ; ++q) {
                o0 = fmaf(e[q], w0[q], o0);
                o1 = fmaf(e[q], w1[q], o1);
            }
            op[(size_t)(2 * c2) * 4096]     = o0;
            op[(size_t)(2 * c2 + 1) * 4096] = o1;
        }
    }
}

// ---------------- launch ------------------------------------------------------
extern "C" void kernel_launch(void* const* d_in, const int* in_sizes, int n_in,
                              void* d_out, int out_size) {
    const float* x     = (const float*)d_in[0];
    const float* style = (const float*)d_in[1];
    const float* dpw   = (const float*)d_in[2];
    const float* dpb   = (const float*)d_in[3];
    const float* s2dw  = (const float*)d_in[4];
    const float* s2db  = (const float*)d_in[5];
    const float* qrot  = (const float*)d_in[6];
    const float* meas  = (const float*)d_in[7];
    const float* opw   = (const float*)d_in[8];
    const float* opb   = (const float*)d_in[9];
    const float* rpw   = (const float*)d_in[10];
    const float* rpb   = (const float*)d_in[11];
    float* out = (float*)d_out;

    cudaFuncSetAttribute(qcnn_main_kernel,
                         cudaFuncAttributeMaxDynamicSharedMemorySize, SM_TOT);

    qcnn_setup_kernel<<<1, 512>>>(style, s2dw, s2db, qrot, meas);
    qcnn_main_kernel<<<dim3(4, 4, 8), 256, SM_TOT>>>(x, dpw, dpb, rpw, rpb,
                                                     opw, opb, out);
}

// round 8
// speedup vs baseline: 1.9687x; 1.0664x over previous
#include <cuda_runtime.h>
#include <cstddef>

#define NQ 6
#define DIM 64
#define PI_F 3.14159265358979323846f

typedef unsigned long long ull;

// ---------------- smem layout (byte offsets) ----------------
static constexpr int SWS     = 76;                     // sW row stride (floats)
static constexpr int OFF_U   = 0;                      // float2[4096]   32768 B
static constexpr int OFF_W   = 32768;                  // float[144*76]  43776 B (also U-build scratch)
static constexpr int OFF_X   = OFF_W + 144 * SWS * 4;  // float[16*342]  21888 B
static constexpr int OFF_ANG = OFF_X + 16 * 342 * 4;   // float[2048]     8192 B
static constexpr int OFF_EV  = OFF_ANG + 8192;         // float[4096]    16384 B
static constexpr int OFF_OW  = OFF_EV + 16384;         // float[384]      1536 B (out_w transposed [q][co])
static constexpr int OFF_B   = OFF_OW + 1536;          // float[64]        256 B (res_b + out_b)
static constexpr int OFF_STY = OFF_B + 256;            // float[8]
static constexpr int OFF_DB  = OFF_STY + 32;           // float[8]
static constexpr int SM_TOT  = OFF_DB + 32;            // 124864 B

__device__ __forceinline__ float2 cmul(float2 a, float2 b) {
    return make_float2(a.x * b.x - a.y * b.y, a.x * b.y + a.y * b.x);
}
__device__ __forceinline__ float2 cadd(float2 a, float2 b) {
    return make_float2(a.x + b.x, a.y + b.y);
}
__device__ __forceinline__ ull pack2(float v) {
    ull r;
    asm("mov.b64 %0, {%1, %1};" : "=l"(r) : "r"(__float_as_uint(v)));
    return r;
}
__device__ __forceinline__ void fma2(ull& d, ull a, ull b) {
    asm("fma.rn.f32x2 %0, %1, %2, %0;" : "+l"(d) : "l"(a), "l"(b));
}
__device__ __forceinline__ float2 unpack2(ull v) {
    float2 f;
    asm("mov.b64 {%0, %1}, %2;" : "=f"(f.x), "=f"(f.y) : "l"(v));
    return f;
}

// ---------------- single fused kernel ----------------------------------------
// 512 threads/CTA, 16x16 pixel tile, grid (4,4,8).
// Thread layout: cg = wid & 7 (8 output channels), pixel-block = (wid>>3)*32+lane
// (2x2 pixels). Quantum: 2 threads per pixel (row halves). U built in-CTA.
__global__ void __launch_bounds__(512, 1) qcnn_fused_kernel(
    const float* __restrict__ x,
    const float* __restrict__ style,
    const float* __restrict__ data_w, const float* __restrict__ data_b,
    const float* __restrict__ s2d_w,  const float* __restrict__ s2d_b,
    const float* __restrict__ qrot,   const float* __restrict__ meas,
    const float* __restrict__ res_w,  const float* __restrict__ res_b,
    const float* __restrict__ out_w,  const float* __restrict__ out_b,
    float* __restrict__ out)
{
    extern __shared__ unsigned char smraw[];
    float2* sU    = reinterpret_cast<float2*>(smraw + OFF_U);
    float*  sW    = reinterpret_cast<float*>(smraw + OFF_W);
    float*  sX    = reinterpret_cast<float*>(smraw + OFF_X);
    float*  sAng  = reinterpret_cast<float*>(smraw + OFF_ANG);
    float*  sEv   = reinterpret_cast<float*>(smraw + OFF_EV);
    float*  sOutWT= reinterpret_cast<float*>(smraw + OFF_OW);
    float*  sBias = reinterpret_cast<float*>(smraw + OFF_B);
    float*  sSty  = reinterpret_cast<float*>(smraw + OFF_STY);
    float*  sDB   = reinterpret_cast<float*>(smraw + OFF_DB);
    float2* S     = reinterpret_cast<float2*>(smraw + OFF_W);  // U-build scratch

    const int tid  = threadIdx.x;
    const int wid  = tid >> 5, lane = tid & 31;
    const int bx = blockIdx.x * 16, by = blockIdx.y * 16, bb = blockIdx.z;

    const int cg  = wid & 7;                  // output-channel group (warp-uniform)
    const int pb  = (wid >> 3) * 32 + lane;   // pixel block 0..63
    const int pbx = pb & 7, pby = pb >> 3;

    // ================= phase 0: build 64x64 circuit unitary in-CTA ===========
    for (int i = tid; i < DIM * DIM; i += 512)
        S[i] = make_float2((i >> 6) == (i & 63) ? 1.f : 0.f, 0.f);
    __syncthreads();

    auto apply = [&](int w, float2 g00, float2 g01, float2 g10, float2 g11) {
        const int m = 1 << (5 - w);
        for (int i = tid; i < 2048; i += 512) {
            int kidx = i >> 6, j = i & 63;
            int k = ((kidx & ~(m - 1)) << 1) | (kidx & (m - 1));
            float2 a0 = S[k * 64 + j], a1 = S[(k | m) * 64 + j];
            S[k * 64 + j]       = cadd(cmul(g00, a0), cmul(g01, a1));
            S[(k | m) * 64 + j] = cadd(cmul(g10, a0), cmul(g11, a1));
        }
        __syncthreads();
    };
    auto cnot = [&](int c, int t) {
        const int mc = 1 << (5 - c), mt = 1 << (5 - t);
        for (int i = tid; i < 4096; i += 512) {
            int k = i >> 6, j = i & 63;
            if ((k & mc) && !(k & mt)) {
                float2 tmp = S[k * 64 + j];
                S[k * 64 + j] = S[(k | mt) * 64 + j];
                S[(k | mt) * 64 + j] = tmp;
            }
        }
        __syncthreads();
    };

    for (int l = 0; l < 2; ++l) {
        for (int i = 0; i < NQ; ++i) {
            float ry = qrot[((l * NQ + i) * 2 + 0) * 3 + 0];
            float c = cosf(0.5f * ry), s = sinf(0.5f * ry);
            apply(i, make_float2(c, 0.f), make_float2(-s, 0.f),
                     make_float2(s, 0.f), make_float2(c, 0.f));
            float rz = qrot[((l * NQ + i) * 2 + 1) * 3 + 0];
            float chh = cosf(0.5f * rz), shh = sinf(0.5f * rz);
            apply(i, make_float2(chh, -shh), make_float2(0.f, 0.f),
                     make_float2(0.f, 0.f), make_float2(chh, shh));
        }
        for (int i = 0; i < NQ; ++i) cnot(i, (i + 1) % NQ);
    }
    for (int i = 0; i < NQ; ++i) {
        float th = meas[i * 3 + 0], ph = meas[i * 3 + 1], la = meas[i * 3 + 2];
        float ct = cosf(0.5f * th), st = sinf(0.5f * th);
        apply(i,
              make_float2(ct, 0.f),
              make_float2(-cosf(la) * st, -sinf(la) * st),
              make_float2(cosf(ph) * st,  sinf(ph) * st),
              make_float2(cosf(ph + la) * ct, sinf(ph + la) * ct));
    }

    // move U out of the sW scratch region; stage small constants
    for (int i = tid; i < DIM * DIM; i += 512) sU[i] = S[i];
    for (int i = tid; i < 384; i += 512) {
        int q = i / 64, co = i & 63;
        sOutWT[i] = out_w[co * NQ + q];
    }
    if (tid < 64) sBias[tid] = res_b[tid] + out_b[tid];
    if (tid < NQ) {
        sDB[tid] = data_b[tid];
        float acc = s2d_b[tid];
        const float* sp = style + bb * 128;
        const float* wp = s2d_w + tid * 128;
#pragma unroll 8
        for (int d = 0; d < 128; ++d) acc = fmaf(sp[d], wp[d], acc);
        sSty[tid] = tanhf(acc) * PI_F;
    }
    // (conv loop's top __syncthreads orders this against sW overwrite)

    // ================= phase 1: conv (res proj + data proj) ==================
    ull acc[4][4];       // 4 pixels x 4 channel-pairs (8 channels)
    float accd[4];       // 4 pixels x 1 data slot (slot index = cg, cg<6)
#pragma unroll
    for (int p = 0; p < 4; ++p) {
        accd[p] = 0.f;
#pragma unroll
        for (int c = 0; c < 4; ++c) acc[p][c] = 0ull;
    }

    for (int ch = 0; ch < 64; ch += 16) {
        __syncthreads();
        // input halo tile [16ch x 18 x 18], padded row stride 19
        for (int i = tid; i < 16 * 324; i += 512) {
            int cl = i / 324, rem = i - cl * 324;
            int r = rem / 18, c = rem - r * 18;
            int gh = by + r - 1, gw = bx + c - 1;
            float v = 0.f;
            if ((unsigned)gh < 64u && (unsigned)gw < 64u)
                v = x[(((size_t)bb * 64 + ch + cl) * 64 + gh) * 64 + gw];
            sX[cl * 342 + r * 19 + c] = v;
        }
        // res weights transposed: sW[p][co]
        for (int i = tid; i < 64 * 144; i += 512) {
            int co = i / 144, p = i - co * 144;
            sW[p * SWS + co] = res_w[(size_t)co * 576 + ch * 9 + p];
        }
        // data weights, 8 slots (2 zero pads)
        for (int i = tid; i < 8 * 144; i += 512) {
            int q = i / 144, p = i - q * 144;
            sW[p * SWS + 64 + q] = (q < 6) ? data_w[(size_t)q * 576 + ch * 9 + p] : 0.f;
        }
        __syncthreads();

        const float* xb = sX + (2 * pby) * 19 + 2 * pbx;
        for (int cl = 0; cl < 16; ++cl) {
            ull w2[16];
#pragma unroll
            for (int y = 0; y < 4; ++y)
#pragma unroll
                for (int xx = 0; xx < 4; ++xx)
                    w2[y * 4 + xx] = pack2(xb[cl * 342 + y * 19 + xx]);

            const float* wb = sW + cl * 9 * SWS;
#pragma unroll
            for (int kp = 0; kp < 9; ++kp) {
                const int ky = kp / 3, kx = kp - ky * 3;
                const ulonglong2* wp =
                    reinterpret_cast<const ulonglong2*>(wb + kp * SWS + cg * 8);
                ulonglong2 wA = wp[0], wB = wp[1];
                float wdS = wb[kp * SWS + 64 + cg];
#pragma unroll
                for (int py = 0; py < 2; ++py)
#pragma unroll
                    for (int pxx = 0; pxx < 2; ++pxx) {
                        const int pi = py * 2 + pxx;
                        ull v = w2[(py + ky) * 4 + (pxx + kx)];
                        fma2(acc[pi][0], v, wA.x);
                        fma2(acc[pi][1], v, wA.y);
                        fma2(acc[pi][2], v, wB.x);
                        fma2(acc[pi][3], v, wB.y);
                        accd[pi] = fmaf(unpack2(v).x, wdS, accd[pi]);
                    }
            }
        }
    }

    // publish data-proj angles (slot = cg for cg<6)
    if (cg < 6) {
#pragma unroll
        for (int pi = 0; pi < 4; ++pi) {
            int py = pi >> 1, pxx = pi & 1;
            int pix = (2 * pby + py) * 16 + 2 * pbx + pxx;
            sAng[pix * 8 + cg] = accd[pi];
        }
    }
    __syncthreads();

    // ================= phase 2: quantum (2 threads per pixel) ================
    {
        const int h   = tid >> 8;     // row half
        const int pix = tid & 255;
        float cw[NQ], sw_[NQ];
#pragma unroll
        for (int q = 0; q < NQ; ++q) {
            float th = tanhf(sAng[pix * 8 + q] + sDB[q]) * PI_F + sSty[q];
            cw[q]  = cosf(0.5f * th);
            sw_[q] = sinf(0.5f * th);
        }
        float A[8], Bv[8];
#pragma unroll
        for (int a = 0; a < 8; ++a) {
            A[a]  = (a & 4 ? sw_[0] : cw[0]) * (a & 2 ? sw_[1] : cw[1]) * (a & 1 ? sw_[2] : cw[2]);
            Bv[a] = (a & 4 ? sw_[3] : cw[3]) * (a & 2 ? sw_[4] : cw[4]) * (a & 1 ? sw_[5] : cw[5]);
        }
        ull adup[8], bdup[8];
#pragma unroll
        for (int a = 0; a < 8; ++a) { adup[a] = pack2(A[a]); bdup[a] = pack2(Bv[a]); }

        float ev[NQ] = {0, 0, 0, 0, 0, 0};
#pragma unroll 4
        for (int rr = 0; rr < 32; ++rr) {
            const int r = h * 32 + rr;
            const ulonglong2* u4 = reinterpret_cast<const ulonglong2*>(sU + r * DIM);
            ull racc = 0ull;
#pragma unroll
            for (int a = 0; a < 8; ++a) {
                ull t = 0ull;
#pragma unroll
                for (int bq = 0; bq < 4; ++bq) {
                    ulonglong2 uu = u4[a * 4 + bq];
                    fma2(t, uu.x, bdup[2 * bq]);
                    fma2(t, uu.y, bdup[2 * bq + 1]);
                }
                fma2(racc, adup[a], t);
            }
            float2 ri = unpack2(racc);
            float pr = fmaf(ri.x, ri.x, ri.y * ri.y);
#pragma unroll
            for (int q = 0; q < NQ; ++q)
                ev[q] += ((r >> (5 - q)) & 1) ? -pr : pr;
        }
#pragma unroll
        for (int q = 0; q < NQ; ++q)
            sEv[h * 2048 + pix * 8 + q] = ev[q];
    }
    __syncthreads();

    // ================= phase 3: epilogue =====================================
    float4 wq[12];   // out_w transposed, this thread's 8 channels x 6 q
#pragma unroll
    for (int q = 0; q < NQ; ++q) {
        const float4* w4 = reinterpret_cast<const float4*>(sOutWT + q * 64 + cg * 8);
        wq[2 * q]     = w4[0];
        wq[2 * q + 1] = w4[1];
    }
    const float4* b4 = reinterpret_cast<const float4*>(sBias + cg * 8);
    float4 biasA = b4[0], biasB = b4[1];

#pragma unroll
    for (int pi = 0; pi < 4; ++pi) {
        int py = pi >> 1, pxx = pi & 1;
        int prow = 2 * pby + py, pcol = 2 * pbx + pxx;
        int pix = prow * 16 + pcol;
        float e[NQ];
#pragma unroll
        for (int q = 0; q < NQ; ++q)
            e[q] = sEv[pix * 8 + q] + sEv[2048 + pix * 8 + q];

        float o[8];
        {
            float2 a0 = unpack2(acc[pi][0]), a1 = unpack2(acc[pi][1]);
            float2 a2 = unpack2(acc[pi][2]), a3 = unpack2(acc[pi][3]);
            o[0] = a0.x + biasA.x; o[1] = a0.y + biasA.y;
            o[2] = a1.x + biasA.z; o[3] = a1.y + biasA.w;
            o[4] = a2.x + biasB.x; o[5] = a2.y + biasB.y;
            o[6] = a3.x + biasB.z; o[7] = a3.y + biasB.w;
        }
#pragma unroll
        for (int q = 0; q < NQ; ++q) {
            float4 wa = wq[2 * q], wb2 = wq[2 * q + 1];
            o[0] = fmaf(e[q], wa.x, o[0]); o[1] = fmaf(e[q], wa.y, o[1]);
            o[2] = fmaf(e[q], wa.z, o[2]); o[3] = fmaf(e[q], wa.w, o[3]);
            o[4] = fmaf(e[q], wb2.x, o[4]); o[5] = fmaf(e[q], wb2.y, o[5]);
            o[6] = fmaf(e[q], wb2.z, o[6]); o[7] = fmaf(e[q], wb2.w, o[7]);
        }
        float* op = out + (size_t)bb * 262144 + (size_t)(cg * 8) * 4096
                        + (by + prow) * 64 + (bx + pcol);
#pragma unroll
        for (int c = 0; c < 8; ++c)
            op[(size_t)c * 4096] = o[c];
    }
}

// ---------------- launch ------------------------------------------------------
extern "C" void kernel_launch(void* const* d_in, const int* in_sizes, int n_in,
                              void* d_out, int out_size) {
    const float* x     = (const float*)d_in[0];
    const float* style = (const float*)d_in[1];
    const float* dpw   = (const float*)d_in[2];
    const float* dpb   = (const float*)d_in[3];
    const float* s2dw  = (const float*)d_in[4];
    const float* s2db  = (const float*)d_in[5];
    const float* qrot  = (const float*)d_in[6];
    const float* meas  = (const float*)d_in[7];
    const float* opw   = (const float*)d_in[8];
    const float* opb   = (const float*)d_in[9];
    const float* rpw   = (const float*)d_in[10];
    const float* rpb   = (const float*)d_in[11];
    float* out = (float*)d_out;

    cudaFuncSetAttribute(qcnn_fused_kernel,
                         cudaFuncAttributeMaxDynamicSharedMemorySize, SM_TOT);

    qcnn_fused_kernel<<<dim3(4, 4, 8), 512, SM_TOT>>>(
        x, style, dpw, dpb, s2dw, s2db, qrot, meas, rpw, rpb, opw, opb, out);
}